// round 15
// baseline (speedup 1.0000x reference)
#include <cuda_runtime.h>
#include <cuda_fp16.h>
#include <mma.h>
#include <cstdint>

using namespace nvcuda;

#define BB    4
#define CCH   256
#define HH    128
#define WWI   416
#define DDI   81
#define PLANE (HH*WWI)
#define MAXD  40

#define MT    64             // M tile
#define KC    16             // channels per chunk (double-buffered)
#define NCH   16             // 256/16
#define NTH   256

#define A_LD  72             // [k][m] halves
#define B_LD  152            // [k][n] halves
#define A_BYTES (KC * A_LD * 2)          // 2304
#define B_BYTES (KC * B_LD * 2)          // 4864
#define BUF_BYTES (A_BYTES + B_BYTES)    // 7168
#define D_LD  148                        // D staging stride (odd word step)
#define D_BYTES (32 * D_LD * 4 + 512)    // 19456
#define SMEM_BYTES D_BYTES               // covers 2*BUF_BYTES (14336) too; 4 CTAs/SM

__global__ __launch_bounds__(NTH, 4)
void corr_pipe3(const float* __restrict__ left,
                const float* __restrict__ right,
                float* __restrict__ out) {
    extern __shared__ __align__(16) char smem[];

    const int tid  = threadIdx.x;
    const int wid  = tid >> 5;
    const int tile = blockIdx.x;                  // 0..6
    const int m0   = (tile == 6) ? 352 : tile * MT;
    const int h    = blockIdx.y, b = blockIdx.z;
    const float* lbase = left  + ((size_t)b * CCH * HH + h) * WWI;
    const float* rbase = right + ((size_t)b * CCH * HH + h) * WWI;

    // warp mapping: wmid = 16-row m stripe; wnid picks 3 of its 6 band n-tiles
    const int wmid  = wid & 3;
    const int wnid  = wid >> 2;
    const int nbase = wmid * 16 + wnid * 48;

    // ---- register staging for one chunk (R13 style: recompute addresses) ----
    float4 rA;
    float4 rB[3];

    auto load_chunk = [&](int c) {
        const int c0 = c * KC;
        {   // A: 256 float4 (16k x 16m4)
            const int k  = tid >> 4;
            const int mi = (tid & 15) * 4;
            rA = *(const float4*)(lbase + (size_t)(c0 + k) * PLANE + m0 + mi);
        }
        #pragma unroll
        for (int i = 0; i < 3; i++) {             // B: 576 float4 (16k x 36)
            const int idx = tid + i * NTH;
            if (idx < 576) {
                const int k  = idx / 36;
                const int n4 = (idx - k * 36) * 4;
                const int wb = m0 - MAXD + n4;
                rB[i] = (wb >= 0 && wb + 3 < WWI)
                      ? *(const float4*)(rbase + (size_t)(c0 + k) * PLANE + wb)
                      : make_float4(0.f, 0.f, 0.f, 0.f);
            }
        }
    };

    auto store_chunk = [&](int buf) {
        __half* As = (__half*)(smem + buf * BUF_BYTES);
        __half* Bs = (__half*)(smem + buf * BUF_BYTES + A_BYTES);
        {
            const int k  = tid >> 4;
            const int mi = (tid & 15) * 4;
            __half2 h0 = __floats2half2_rn(rA.x, rA.y);
            __half2 h1 = __floats2half2_rn(rA.z, rA.w);
            *(uint2*)(As + k * A_LD + mi) = make_uint2(*(uint32_t*)&h0, *(uint32_t*)&h1);
        }
        #pragma unroll
        for (int i = 0; i < 3; i++) {
            const int idx = tid + i * NTH;
            if (idx < 576) {
                const int k  = idx / 36;
                const int n4 = (idx - k * 36) * 4;
                __half2 h0 = __floats2half2_rn(rB[i].x, rB[i].y);
                __half2 h1 = __floats2half2_rn(rB[i].z, rB[i].w);
                *(uint2*)(Bs + k * B_LD + n4) = make_uint2(*(uint32_t*)&h0, *(uint32_t*)&h1);
            }
        }
    };

    wmma::fragment<wmma::accumulator, 16, 16, 16, float> acc[3];
    #pragma unroll
    for (int j = 0; j < 3; j++) wmma::fill_fragment(acc[j], 0.0f);

    // prologue: chunk 0 into buffer 0
    load_chunk(0);
    store_chunk(0);
    __syncthreads();

    for (int c = 0; c < NCH; c++) {
        const int buf = c & 1;

        if (c + 1 < NCH) load_chunk(c + 1);        // LDGs for c+1 before MMA on c

        const __half* As = (const __half*)(smem + buf * BUF_BYTES);
        const __half* Bs = (const __half*)(smem + buf * BUF_BYTES + A_BYTES);
        {
            wmma::fragment<wmma::matrix_a, 16, 16, 16, __half, wmma::col_major> af;
            wmma::load_matrix_sync(af, As + wmid * 16, A_LD);
            #pragma unroll
            for (int j = 0; j < 3; j++) {
                wmma::fragment<wmma::matrix_b, 16, 16, 16, __half, wmma::row_major> bf;
                wmma::load_matrix_sync(bf, Bs + nbase + j * 16, B_LD);
                wmma::mma_sync(acc[j], af, bf, acc[j]);
            }
        }

        if (c + 1 < NCH) store_chunk(buf ^ 1);     // cvt+STS after MMA (LDGs landed)
        __syncthreads();
    }

    // ---- scale by 1/256 (exact power of two) ----
    #pragma unroll
    for (int j = 0; j < 3; j++)
        #pragma unroll
        for (int e = 0; e < acc[j].num_elements; e++) acc[j].x[e] *= (1.0f / 256.0f);

    // ---- epilogue in two m-half passes; Ds = [32][148] f32 = 18944 B ----
    float* Ds = (float*)smem;
    const int ms = (tile == 6) ? 32 : 0;          // mask overlap with tile 5
    #pragma unroll
    for (int half = 0; half < 2; half++) {
        if ((wmid >> 1) == half) {
            const int rrow = (wmid & 1) * 16;
            #pragma unroll
            for (int j = 0; j < 3; j++)
                wmma::store_matrix_sync(Ds + rrow * D_LD + nbase + j * 16,
                                        acc[j], D_LD, wmma::mem_row_major);
        }
        __syncthreads();

        const int ml = tid & 31;
        const int m  = half * 32 + ml;
        if (m >= ms) {
            for (int d = tid >> 5; d < DDI; d += 8) {
                out[(((size_t)b * DDI + d) * HH + h) * WWI + m0 + m] = Ds[ml * D_LD + m + d];
            }
        }
        __syncthreads();
    }
}

extern "C" void kernel_launch(void* const* d_in, const int* in_sizes, int n_in,
                              void* d_out, int out_size) {
    const float* left  = (const float*)d_in[0];
    const float* right = (const float*)d_in[1];
    float* out = (float*)d_out;
    (void)in_sizes; (void)n_in; (void)out_size;

    cudaFuncSetAttribute(corr_pipe3, cudaFuncAttributeMaxDynamicSharedMemorySize, SMEM_BYTES);
    dim3 grid(7, HH, BB);    // (m-tiles, h, b) = 3584 CTAs
    corr_pipe3<<<grid, NTH, SMEM_BYTES>>>(left, right, out);
}

// round 16
// speedup vs baseline: 1.0613x; 1.0613x over previous
#include <cuda_runtime.h>
#include <cuda_fp16.h>
#include <mma.h>
#include <cstdint>

using namespace nvcuda;

#define BB    4
#define CCH   256
#define HH    128
#define WWI   416
#define DDI   81
#define PLANE (HH*WWI)
#define MAXD  40

#define MT    64             // M tile
#define KC    32             // channels per chunk (double-buffered)
#define NCH   8              // 256/32
#define NTH   256

#define A_LD  72             // [k][m] halves
#define B_LD  152            // [k][n] halves
#define A_BYTES (KC * A_LD * 2)          // 4608
#define B_BYTES (KC * B_LD * 2)          // 9728
#define BUF_BYTES (A_BYTES + B_BYTES)    // 14336
#define SMEM_BYTES (2 * BUF_BYTES)       // 28672

#define D_LD  148            // D staging stride (149-word row step, odd -> conflict-free)

__global__ __launch_bounds__(NTH, 3)
void corr_pipe4(const float* __restrict__ left,
                const float* __restrict__ right,
                float* __restrict__ out) {
    extern __shared__ __align__(16) char smem[];

    const int tid  = threadIdx.x;
    const int wid  = tid >> 5;
    const int tile = blockIdx.x;                  // 0..6
    const int m0   = (tile == 6) ? 352 : tile * MT;
    const int h    = blockIdx.y, b = blockIdx.z;
    const float* lbase = left  + ((size_t)b * CCH * HH + h) * WWI;
    const float* rbase = right + ((size_t)b * CCH * HH + h) * WWI;

    // warp mapping: wmid = 16-row m stripe; wnid picks 3 of its 6 band n-tiles
    const int wmid  = wid & 3;
    const int wnid  = wid >> 2;
    const int nbase = wmid * 16 + wnid * 48;

    // ---- register staging: 8 floats per slot (2x LDG.128 -> 1x STS.128) ----
    float4 rA[2];                                  // A: 1 slot of 8 floats
    float4 rB[3][2];                               // B: 3 slots of 8 floats

    auto load_chunk = [&](int c) {
        const int c0 = c * KC;
        {   // A: 32k x 8 slots (8 floats each); k=tid>>3, mi=(tid&7)*8
            const int k  = tid >> 3;
            const int mi = (tid & 7) * 8;
            const float* g = lbase + (size_t)(c0 + k) * PLANE + m0 + mi;
            rA[0] = *(const float4*)g;
            rA[1] = *(const float4*)(g + 4);
        }
        #pragma unroll
        for (int i = 0; i < 3; i++) {              // B: 576 pair-slots (32k x 18)
            const int idx = tid + i * NTH;
            if (idx < 576) {
                const int k  = idx / 18;
                const int n8 = (idx - k * 18) * 8;
                const int wb = m0 - MAXD + n8;
                if (wb >= 0 && wb + 8 <= WWI) {    // 8-aligned: all-in or all-out
                    const float* g = rbase + (size_t)(c0 + k) * PLANE + wb;
                    rB[i][0] = *(const float4*)g;
                    rB[i][1] = *(const float4*)(g + 4);
                } else {
                    rB[i][0] = make_float4(0.f, 0.f, 0.f, 0.f);
                    rB[i][1] = make_float4(0.f, 0.f, 0.f, 0.f);
                }
            }
        }
    };

    auto store_chunk = [&](int buf) {
        __half* As = (__half*)(smem + buf * BUF_BYTES);
        __half* Bs = (__half*)(smem + buf * BUF_BYTES + A_BYTES);
        {
            const int k  = tid >> 3;
            const int mi = (tid & 7) * 8;
            __half2 h0 = __floats2half2_rn(rA[0].x, rA[0].y);
            __half2 h1 = __floats2half2_rn(rA[0].z, rA[0].w);
            __half2 h2 = __floats2half2_rn(rA[1].x, rA[1].y);
            __half2 h3 = __floats2half2_rn(rA[1].z, rA[1].w);
            uint4 v = make_uint4(*(uint32_t*)&h0, *(uint32_t*)&h1,
                                 *(uint32_t*)&h2, *(uint32_t*)&h3);
            *(uint4*)(As + k * A_LD + mi) = v;     // 16B aligned
        }
        #pragma unroll
        for (int i = 0; i < 3; i++) {
            const int idx = tid + i * NTH;
            if (idx < 576) {
                const int k  = idx / 18;
                const int n8 = (idx - k * 18) * 8;
                __half2 h0 = __floats2half2_rn(rB[i][0].x, rB[i][0].y);
                __half2 h1 = __floats2half2_rn(rB[i][0].z, rB[i][0].w);
                __half2 h2 = __floats2half2_rn(rB[i][1].x, rB[i][1].y);
                __half2 h3 = __floats2half2_rn(rB[i][1].z, rB[i][1].w);
                uint4 v = make_uint4(*(uint32_t*)&h0, *(uint32_t*)&h1,
                                     *(uint32_t*)&h2, *(uint32_t*)&h3);
                *(uint4*)(Bs + k * B_LD + n8) = v; // 16B aligned
            }
        }
    };

    wmma::fragment<wmma::accumulator, 16, 16, 16, float> acc[3];
    #pragma unroll
    for (int j = 0; j < 3; j++) wmma::fill_fragment(acc[j], 0.0f);

    // prologue: chunk 0 into buffer 0
    load_chunk(0);
    store_chunk(0);
    __syncthreads();

    for (int c = 0; c < NCH; c++) {
        const int buf = c & 1;

        if (c + 1 < NCH) load_chunk(c + 1);        // LDG burst for c+1 before MMA on c

        const __half* As = (const __half*)(smem + buf * BUF_BYTES);
        const __half* Bs = (const __half*)(smem + buf * BUF_BYTES + A_BYTES);
        #pragma unroll
        for (int kt = 0; kt < KC / 16; kt++) {
            wmma::fragment<wmma::matrix_a, 16, 16, 16, __half, wmma::col_major> af;
            wmma::load_matrix_sync(af, As + kt * 16 * A_LD + wmid * 16, A_LD);
            #pragma unroll
            for (int j = 0; j < 3; j++) {
                wmma::fragment<wmma::matrix_b, 16, 16, 16, __half, wmma::row_major> bf;
                wmma::load_matrix_sync(bf, Bs + kt * 16 * B_LD + nbase + j * 16, B_LD);
                wmma::mma_sync(acc[j], af, bf, acc[j]);
            }
        }

        if (c + 1 < NCH) store_chunk(buf ^ 1);     // cvt+STS.128 after MMA
        __syncthreads();
    }

    // ---- scale by 1/256 (exact power of two) ----
    #pragma unroll
    for (int j = 0; j < 3; j++)
        #pragma unroll
        for (int e = 0; e < acc[j].num_elements; e++) acc[j].x[e] *= (1.0f / 256.0f);

    // ---- epilogue in two m-half passes; Ds = [32][148] f32 = 18944 B ----
    float* Ds = (float*)smem;
    const int ms = (tile == 6) ? 32 : 0;          // mask overlap with tile 5
    #pragma unroll
    for (int half = 0; half < 2; half++) {
        if ((wmid >> 1) == half) {
            const int rrow = (wmid & 1) * 16;
            #pragma unroll
            for (int j = 0; j < 3; j++)
                wmma::store_matrix_sync(Ds + rrow * D_LD + nbase + j * 16,
                                        acc[j], D_LD, wmma::mem_row_major);
        }
        __syncthreads();

        const int ml = tid & 31;
        const int m  = half * 32 + ml;
        if (m >= ms) {
            for (int d = tid >> 5; d < DDI; d += 8) {
                out[(((size_t)b * DDI + d) * HH + h) * WWI + m0 + m] = Ds[ml * D_LD + m + d];
            }
        }
        __syncthreads();
    }
}

extern "C" void kernel_launch(void* const* d_in, const int* in_sizes, int n_in,
                              void* d_out, int out_size) {
    const float* left  = (const float*)d_in[0];
    const float* right = (const float*)d_in[1];
    float* out = (float*)d_out;
    (void)in_sizes; (void)n_in; (void)out_size;

    cudaFuncSetAttribute(corr_pipe4, cudaFuncAttributeMaxDynamicSharedMemorySize, SMEM_BYTES);
    dim3 grid(7, HH, BB);    // (m-tiles, h, b) = 3584 CTAs
    corr_pipe4<<<grid, NTH, SMEM_BYTES>>>(left, right, out);
}